// round 2
// baseline (speedup 1.0000x reference)
#include <cuda_runtime.h>
#include <cuda_bf16.h>

static constexpr int CCH = 64;
static constexpr int HH  = 480;
static constexpr int WW  = 640;
static constexpr long long HWSZ = (long long)HH * WW;   // 307200
static constexpr long long NV   = 256LL * 256 * 32;     // 2097152 voxels

// Scratch: transposed features, xT[pixel * 64 + channel]  (75 MB)
__device__ float g_xT[(size_t)HWSZ * CCH];

// ---------------------------------------------------------------------------
// Transpose x2d (C, H*W) -> xT (H*W, C). Tiled via smem, conflict-free.
// Grid: HW/64 blocks, block (64, 4).
// ---------------------------------------------------------------------------
__global__ void __launch_bounds__(256) k_transpose(const float* __restrict__ x2d)
{
    __shared__ float tile[64][65];
    const int pbase = blockIdx.x * 64;
    const int tx = threadIdx.x;   // 0..63
    const int ty = threadIdx.y;   // 0..3

#pragma unroll
    for (int cc = 0; cc < 64; cc += 4)
        tile[cc + ty][tx] = x2d[(long long)(cc + ty) * HWSZ + pbase + tx];
    __syncthreads();
#pragma unroll
    for (int qq = 0; qq < 64; qq += 4)
        g_xT[(long long)(pbase + qq + ty) * CCH + tx] = tile[tx][qq + ty];
}

// ---------------------------------------------------------------------------
// Main fused kernel: each thread handles 4 consecutive voxels.
// Reads 4 x 256B contiguous feature rows from xT (perfect sector use),
// writes 64 channel planes with float4 stores coalesced across the warp.
// ---------------------------------------------------------------------------
__global__ void __launch_bounds__(256) k_fuse(
    const int*   __restrict__ ppix,     // (N, 2) int32 : x, y
    const int*   __restrict__ scale_p,  // scalar int32
    const int*   __restrict__ mask,     // (N,) int32 (bool)
    const float* __restrict__ pz,       // (N,) float32
    const float* __restrict__ depth,    // (H*W,) float32
    float*       __restrict__ out)      // (64, N) float32
{
    const long long t  = (long long)blockIdx.x * blockDim.x + threadIdx.x;
    const long long i0 = t * 4;
    if (i0 >= NV) return;

    const int scale = scale_p[0];

    const int4   pa = reinterpret_cast<const int4*>(ppix)[t * 2 + 0];
    const int4   pb = reinterpret_cast<const int4*>(ppix)[t * 2 + 1];
    const int4   mk = reinterpret_cast<const int4*>(mask)[t];
    const float4 zz = reinterpret_cast<const float4*>(pz)[t];

    const int px[4] = {pa.x, pa.z, pb.x, pb.z};
    const int py[4] = {pa.y, pa.w, pb.y, pb.w};
    const int mv[4] = {mk.x, mk.y, mk.z, mk.w};
    const float zv[4] = {zz.x, zz.y, zz.z, zz.w};

    long long fbase[4];
    float wgt[4];
#pragma unroll
    for (int j = 0; j < 4; j++) {
        const int di = py[j] * WW + px[j];
        const int fi = (scale == 1) ? di : ((py[j] / scale) * WW + (px[j] / scale));
        fbase[j] = (long long)fi * CCH;
        const float dv = mv[j] ? __ldg(depth + di) : 0.0f;
        const float d  = zv[j] - dv;
        const float gw = __expf(-0.5f * d * d);       // sigma = 1/PROJECT_SCALE = 1
        const float wv = (dv == 0.0f) ? 1.0f : gw;
        wgt[j] = mv[j] ? wv : 0.0f;
    }

    const float4* s0 = reinterpret_cast<const float4*>(g_xT + fbase[0]);
    const float4* s1 = reinterpret_cast<const float4*>(g_xT + fbase[1]);
    const float4* s2 = reinterpret_cast<const float4*>(g_xT + fbase[2]);
    const float4* s3 = reinterpret_cast<const float4*>(g_xT + fbase[3]);
    float* ob = out + i0;

#pragma unroll 4
    for (int cg = 0; cg < 16; cg++) {
        const float4 a = __ldg(s0 + cg);
        const float4 b = __ldg(s1 + cg);
        const float4 c = __ldg(s2 + cg);
        const float4 d = __ldg(s3 + cg);

        float4 o0 = make_float4(a.x * wgt[0], b.x * wgt[1], c.x * wgt[2], d.x * wgt[3]);
        float4 o1 = make_float4(a.y * wgt[0], b.y * wgt[1], c.y * wgt[2], d.y * wgt[3]);
        float4 o2 = make_float4(a.z * wgt[0], b.z * wgt[1], c.z * wgt[2], d.z * wgt[3]);
        float4 o3 = make_float4(a.w * wgt[0], b.w * wgt[1], c.w * wgt[2], d.w * wgt[3]);

        *reinterpret_cast<float4*>(ob + (long long)(cg * 4 + 0) * NV) = o0;
        *reinterpret_cast<float4*>(ob + (long long)(cg * 4 + 1) * NV) = o1;
        *reinterpret_cast<float4*>(ob + (long long)(cg * 4 + 2) * NV) = o2;
        *reinterpret_cast<float4*>(ob + (long long)(cg * 4 + 3) * NV) = o3;
    }
}

extern "C" void kernel_launch(void* const* d_in, const int* in_sizes, int n_in,
                              void* d_out, int out_size)
{
    const float* x2d   = (const float*)d_in[0];   // (64, 480, 640) f32
    const int*   ppix  = (const int*)  d_in[1];   // (N, 2) i32
    const int*   scale = (const int*)  d_in[2];   // scalar i32
    const int*   mask  = (const int*)  d_in[3];   // (N,) bool->i32 (assumed)
    const float* pz    = (const float*)d_in[4];   // (N,) f32
    const float* depth = (const float*)d_in[5];   // (1, 480, 640) f32
    float* out = (float*)d_out;

    k_transpose<<<(int)(HWSZ / 64), dim3(64, 4)>>>(x2d);

    const int threads = 256;
    const int blocks  = (int)((NV / 4 + threads - 1) / threads);
    k_fuse<<<blocks, threads>>>(ppix, scale, mask, pz, depth, out);
}

// round 4
// speedup vs baseline: 1.6860x; 1.6860x over previous
#include <cuda_runtime.h>
#include <cuda_bf16.h>

static constexpr int CCH = 64;
static constexpr int HH  = 480;
static constexpr int WW  = 640;
static constexpr long long HWSZ = (long long)HH * WW;   // 307200
static constexpr long long NV   = 256LL * 256 * 32;     // 2097152 voxels
static constexpr int TILE = 128;                        // voxels per block

// Scratch: transposed features, xT[pixel * 64 + channel]  (75 MB, L2-resident)
__device__ float g_xT[(size_t)HWSZ * CCH];

// ---------------------------------------------------------------------------
// Transpose x2d (C, H*W) -> xT (H*W, C). Tiled via smem, conflict-free.
// ---------------------------------------------------------------------------
__global__ void __launch_bounds__(256) k_transpose(const float* __restrict__ x2d)
{
    __shared__ float tile[64][65];
    const int pbase = blockIdx.x * 64;
    const int tx = threadIdx.x;   // 0..63
    const int ty = threadIdx.y;   // 0..3

#pragma unroll
    for (int cc = 0; cc < 64; cc += 4)
        tile[cc + ty][tx] = x2d[(long long)(cc + ty) * HWSZ + pbase + tx];
    __syncthreads();
#pragma unroll
    for (int qq = 0; qq < 64; qq += 4)
        g_xT[(long long)(pbase + qq + ty) * CCH + tx] = tile[tx][qq + ty];
}

// ---------------------------------------------------------------------------
// Fused kernel, smem-staged:
//  Phase A: 128 threads compute per-voxel feature index + Gaussian weight.
//  Phase B: warp-cooperative gather — 16 lanes read one 256B voxel row
//           (LDG.128 per lane, 4 wavefronts / 2 voxels) -> smem transpose.
//  Phase C: coalesced stores — lanes vary voxel (stride 1), conflict-free
//           LDS (pitch 65), 128B-coalesced STG.32 per channel plane.
// ---------------------------------------------------------------------------
__global__ void __launch_bounds__(256) k_fuse(
    const int*   __restrict__ ppix,     // (N, 2) int32 : x, y
    const int*   __restrict__ scale_p,  // scalar int32
    const int*   __restrict__ mask,     // (N,) int32 (bool)
    const float* __restrict__ pz,       // (N,) float32
    const float* __restrict__ depth,    // (H*W,) float32
    float*       __restrict__ out)      // (64, N) float32
{
    __shared__ float sm_feat[TILE][CCH + 1];   // pitch 65
    __shared__ float sm_w[TILE];
    __shared__ int   sm_fidx[TILE];

    const int tid = threadIdx.x;
    const long long vbase = (long long)blockIdx.x * TILE;

    // ---- Phase A: indices + weights (threads 0..127) ----
    if (tid < TILE) {
        const long long i = vbase + tid;
        const int2 p = reinterpret_cast<const int2*>(ppix)[i];
        const int  m = mask[i];
        const float z = pz[i];
        const int scale = scale_p[0];
        const int di = p.y * WW + p.x;
        const int fi = (scale == 1) ? di : ((p.y / scale) * WW + (p.x / scale));
        sm_fidx[tid] = fi;
        const float dv = m ? __ldg(depth + di) : 0.0f;
        const float d  = z - dv;
        const float gw = __expf(-0.5f * d * d);   // sigma = 1
        sm_w[tid] = m ? ((dv == 0.0f) ? 1.0f : gw) : 0.0f;
    }
    __syncthreads();

    // ---- Phase B: cooperative gather (16 lanes per voxel row) ----
    {
        const int vt = tid >> 4;        // 0..15: voxel-in-group
        const int kk = tid & 15;        // 0..15: float4 index within row
#pragma unroll
        for (int it = 0; it < TILE / 16; it++) {
            const int v = it * 16 + vt;
            const float4 f = __ldg(
                reinterpret_cast<const float4*>(g_xT + (long long)sm_fidx[v] * CCH) + kk);
            float* dst = &sm_feat[v][kk * 4];
            dst[0] = f.x; dst[1] = f.y; dst[2] = f.z; dst[3] = f.w;
        }
    }
    __syncthreads();

    // ---- Phase C: coalesced weighted stores ----
    {
        const int vv  = tid & (TILE - 1);   // 0..127: voxel
        const int ch0 = tid >> 7;           // 0 or 1
        const float wv = sm_w[vv];
        float* op = out + vbase + vv;
#pragma unroll
        for (int it = 0; it < CCH / 2; it++) {
            const int c = it * 2 + ch0;
            op[(long long)c * NV] = sm_feat[vv][c] * wv;
        }
    }
}

extern "C" void kernel_launch(void* const* d_in, const int* in_sizes, int n_in,
                              void* d_out, int out_size)
{
    const float* x2d   = (const float*)d_in[0];   // (64, 480, 640) f32
    const int*   ppix  = (const int*)  d_in[1];   // (N, 2) i32
    const int*   scale = (const int*)  d_in[2];   // scalar i32
    const int*   mask  = (const int*)  d_in[3];   // (N,) i32
    const float* pz    = (const float*)d_in[4];   // (N,) f32
    const float* depth = (const float*)d_in[5];   // (1, 480, 640) f32
    float* out = (float*)d_out;

    k_transpose<<<(int)(HWSZ / 64), dim3(64, 4)>>>(x2d);

    k_fuse<<<(int)(NV / TILE), 256>>>(ppix, scale, mask, pz, depth, out);
}

// round 5
// speedup vs baseline: 2.0990x; 1.2450x over previous
#include <cuda_runtime.h>
#include <cuda_fp16.h>
#include <cuda_bf16.h>

static constexpr int CCH = 64;
static constexpr int HH  = 480;
static constexpr int WW  = 640;
static constexpr long long HWSZ = (long long)HH * WW;   // 307200
static constexpr long long NV   = 256LL * 256 * 32;     // 2097152 voxels
static constexpr int TILE = 128;                        // voxels per block

// Scratch: transposed fp16 features, xTh[pixel * 64 + channel]  (39 MB, L2-resident)
__device__ __align__(16) __half g_xTh[(size_t)HWSZ * CCH];

// ---------------------------------------------------------------------------
// Transpose x2d (C, H*W) f32 -> xTh (H*W, C) f16. Tiled via smem.
// Block (64,4): 64 pixels x 64 channels per block.
// ---------------------------------------------------------------------------
__global__ void __launch_bounds__(256) k_transpose(const float* __restrict__ x2d)
{
    __shared__ float tile[64][65];        // tile[channel][pixel]
    const int pbase = blockIdx.x * 64;
    const int tx = threadIdx.x;   // 0..63
    const int ty = threadIdx.y;   // 0..3
    const int tid  = ty * 64 + tx;
    const int lane = tid & 31;
    const int w    = tid >> 5;    // 0..7

#pragma unroll
    for (int cc = 0; cc < 64; cc += 4)
        tile[cc + ty][tx] = x2d[(long long)(cc + ty) * HWSZ + pbase + tx];
    __syncthreads();

    // Write phase: one warp per pixel row, each lane packs 2 channels -> half2.
    __half2* xT2 = reinterpret_cast<__half2*>(g_xTh);
#pragma unroll
    for (int it = 0; it < 8; it++) {
        const int p  = it * 8 + w;
        const int c2 = lane * 2;
        const __half2 h = __floats2half2_rn(tile[c2][p], tile[c2 + 1][p]);
        xT2[(long long)(pbase + p) * 32 + lane] = h;
    }
}

// ---------------------------------------------------------------------------
// Fused kernel, smem-staged:
//  Phase A: per-voxel feature index + Gaussian weight.
//  Phase B: warp-cooperative gather — 8 lanes read one 128B fp16 voxel row;
//           a warp LDG.128 covers 4 voxels (1 L1 wavefront / voxel).
//  Phase C: conflict-free LDS + coalesced streaming STG.32 per channel plane.
// ---------------------------------------------------------------------------
__global__ void __launch_bounds__(256) k_fuse(
    const int*   __restrict__ ppix,     // (N, 2) int32 : x, y
    const int*   __restrict__ scale_p,  // scalar int32
    const int*   __restrict__ mask,     // (N,) int32 (bool)
    const float* __restrict__ pz,       // (N,) float32
    const float* __restrict__ depth,    // (H*W,) float32
    float*       __restrict__ out)      // (64, N) float32
{
    __shared__ float sm_feat[TILE][CCH + 1];   // pitch 65
    __shared__ float sm_w[TILE];
    __shared__ int   sm_fidx[TILE];

    const int tid = threadIdx.x;
    const long long vbase = (long long)blockIdx.x * TILE;

    // ---- Phase A: indices + weights (threads 0..127) ----
    if (tid < TILE) {
        const long long i = vbase + tid;
        const int2 p = reinterpret_cast<const int2*>(ppix)[i];
        const int  m = mask[i];
        const float z = pz[i];
        const int scale = scale_p[0];
        const int di = p.y * WW + p.x;
        const int fi = (scale == 1) ? di : ((p.y / scale) * WW + (p.x / scale));
        sm_fidx[tid] = fi;
        const float dv = m ? __ldg(depth + di) : 0.0f;
        const float d  = z - dv;
        const float gw = __expf(-0.5f * d * d);   // sigma = 1
        sm_w[tid] = m ? ((dv == 0.0f) ? 1.0f : gw) : 0.0f;
    }
    __syncthreads();

    // ---- Phase B: cooperative gather (8 lanes per 128B fp16 voxel row) ----
    {
        const int vt = tid >> 3;        // 0..31: voxel-in-group
        const int kk = tid & 7;         // 0..7 : float4 (8 halves) within row
#pragma unroll
        for (int it = 0; it < TILE / 32; it++) {
            const int v = it * 32 + vt;
            const float4 f = __ldg(
                reinterpret_cast<const float4*>(g_xTh + (long long)sm_fidx[v] * CCH) + kk);
            const __half2* hp = reinterpret_cast<const __half2*>(&f);
            float* dst = &sm_feat[v][kk * 8];
#pragma unroll
            for (int j = 0; j < 4; j++) {
                const float2 fv = __half22float2(hp[j]);
                dst[2 * j]     = fv.x;
                dst[2 * j + 1] = fv.y;
            }
        }
    }
    __syncthreads();

    // ---- Phase C: coalesced weighted streaming stores ----
    {
        const int vv  = tid & (TILE - 1);   // 0..127: voxel
        const int ch0 = tid >> 7;           // 0 or 1
        const float wv = sm_w[vv];
        float* op = out + vbase + vv;
#pragma unroll
        for (int it = 0; it < CCH / 2; it++) {
            const int c = it * 2 + ch0;
            __stcs(op + (long long)c * NV, sm_feat[vv][c] * wv);
        }
    }
}

extern "C" void kernel_launch(void* const* d_in, const int* in_sizes, int n_in,
                              void* d_out, int out_size)
{
    const float* x2d   = (const float*)d_in[0];   // (64, 480, 640) f32
    const int*   ppix  = (const int*)  d_in[1];   // (N, 2) i32
    const int*   scale = (const int*)  d_in[2];   // scalar i32
    const int*   mask  = (const int*)  d_in[3];   // (N,) i32
    const float* pz    = (const float*)d_in[4];   // (N,) f32
    const float* depth = (const float*)d_in[5];   // (1, 480, 640) f32
    float* out = (float*)d_out;

    k_transpose<<<(int)(HWSZ / 64), dim3(64, 4)>>>(x2d);

    k_fuse<<<(int)(NV / TILE), 256>>>(ppix, scale, mask, pz, depth, out);
}

// round 8
// speedup vs baseline: 2.4205x; 1.1531x over previous
#include <cuda_runtime.h>
#include <cuda_fp16.h>
#include <cuda_bf16.h>
#include <cstdint>

static constexpr int CCH = 64;
static constexpr int HH  = 480;
static constexpr int WW  = 640;
static constexpr long long HWSZ = (long long)HH * WW;   // 307200
static constexpr long long NV   = 256LL * 256 * 32;     // 2097152 voxels
static constexpr int TILE = 128;                        // voxels per block
static constexpr int PITCH = 66;                        // halves per smem row (132B)

// Scratch: transposed fp16 features, xTh[pixel * 64 + channel]  (39 MB, L2-resident)
__device__ __align__(16) __half g_xTh[(size_t)HWSZ * CCH];

// ---------------------------------------------------------------------------
// Transpose x2d (C, H*W) f32 -> xTh (H*W, C) f16. Tiled via smem.
// ---------------------------------------------------------------------------
__global__ void __launch_bounds__(256) k_transpose(const float* __restrict__ x2d)
{
    __shared__ float tile[64][65];        // tile[channel][pixel]
    const int pbase = blockIdx.x * 64;
    const int tx = threadIdx.x;   // 0..63
    const int ty = threadIdx.y;   // 0..3
    const int tid  = ty * 64 + tx;
    const int lane = tid & 31;
    const int w    = tid >> 5;    // 0..7

#pragma unroll
    for (int cc = 0; cc < 64; cc += 4)
        tile[cc + ty][tx] = x2d[(long long)(cc + ty) * HWSZ + pbase + tx];
    __syncthreads();

    __half2* xT2 = reinterpret_cast<__half2*>(g_xTh);
#pragma unroll
    for (int it = 0; it < 8; it++) {
        const int p  = it * 8 + w;
        const int c2 = lane * 2;
        const __half2 h = __floats2half2_rn(tile[c2][p], tile[c2 + 1][p]);
        xT2[(long long)(pbase + p) * 32 + lane] = h;
    }
}

// ---------------------------------------------------------------------------
// Fused kernel, fp16 end-to-end smem staging:
//  Phase A: per-voxel feature index + Gaussian weight (128 threads).
//  Phase B: warp-cooperative gather — 8 lanes read one 128B fp16 voxel row
//           (LDG.128); raw fp16 words go straight to smem (4 STS.32,
//           conflict-free). Masked voxels skip the LDG, store zeros.
//  Phase C: one LDS.32 = half2 (2 channels) per iter, conflict-free;
//           convert + weight + 2 coalesced streaming STG.32.
// ---------------------------------------------------------------------------
__global__ void __launch_bounds__(256) k_fuse(
    const int*   __restrict__ ppix,     // (N, 2) int32 : x, y
    const int*   __restrict__ scale_p,  // scalar int32
    const int*   __restrict__ mask,     // (N,) int32 (bool)
    const float* __restrict__ pz,       // (N,) float32
    const float* __restrict__ depth,    // (H*W,) float32
    float*       __restrict__ out)      // (64, N) float32
{
    __shared__ __align__(16) __half sm16[TILE][PITCH];
    __shared__ float sm_w[TILE];
    __shared__ int   sm_fidx[TILE];

    uint32_t* su = reinterpret_cast<uint32_t*>(&sm16[0][0]);
    const int tid = threadIdx.x;
    const long long vbase = (long long)blockIdx.x * TILE;

    // ---- Phase A: indices + weights (threads 0..127) ----
    if (tid < TILE) {
        const long long i = vbase + tid;
        const int2 p = reinterpret_cast<const int2*>(ppix)[i];
        const int  m = mask[i];
        const float z = pz[i];
        const int scale = scale_p[0];
        const int di = p.y * WW + p.x;
        const int fi = (scale == 1) ? di : ((p.y / scale) * WW + (p.x / scale));
        sm_fidx[tid] = fi;
        const float dv = m ? __ldg(depth + di) : 0.0f;
        const float d  = z - dv;
        const float gw = __expf(-0.5f * d * d);   // sigma = 1
        sm_w[tid] = m ? ((dv == 0.0f) ? 1.0f : gw) : 0.0f;
    }
    __syncthreads();

    // ---- Phase B: cooperative gather, raw fp16 -> smem ----
    {
        const int vt = tid >> 3;        // 0..31: voxel slot within group
        const int kk = tid & 7;         // 0..7 : 16B chunk within 128B row
#pragma unroll
        for (int it = 0; it < TILE / 32; it++) {
            const int v = it * 32 + vt;
            uint4 r = make_uint4(0u, 0u, 0u, 0u);
            if (sm_w[v] != 0.0f)
                r = __ldg(reinterpret_cast<const uint4*>(
                        g_xTh + (long long)sm_fidx[v] * CCH) + kk);
            const int wbase = v * (PITCH / 2) + 4 * kk;  // 32-bit word index
            su[wbase + 0] = r.x;
            su[wbase + 1] = r.y;
            su[wbase + 2] = r.z;
            su[wbase + 3] = r.w;
        }
    }
    __syncthreads();

    // ---- Phase C: half2 loads, weighted, coalesced streaming stores ----
    {
        const int vv = tid & (TILE - 1);   // 0..127: voxel (contig per warp)
        const int hp = tid >> 7;           // 0 or 1: channel-pair split
        const float wv = sm_w[vv];
        float* op = out + vbase + vv;
        const int wrow = vv * (PITCH / 2);
#pragma unroll
        for (int it = 0; it < 16; it++) {
            const int c = it * 4 + hp * 2;            // even channel
            const uint32_t bits = su[wrow + (c >> 1)];
            const float2 f = __half22float2(*reinterpret_cast<const __half2*>(&bits));
            __stcs(op + (long long)c * NV,       f.x * wv);
            __stcs(op + (long long)(c + 1) * NV, f.y * wv);
        }
    }
}

extern "C" void kernel_launch(void* const* d_in, const int* in_sizes, int n_in,
                              void* d_out, int out_size)
{
    const float* x2d   = (const float*)d_in[0];   // (64, 480, 640) f32
    const int*   ppix  = (const int*)  d_in[1];   // (N, 2) i32
    const int*   scale = (const int*)  d_in[2];   // scalar i32
    const int*   mask  = (const int*)  d_in[3];   // (N,) i32
    const float* pz    = (const float*)d_in[4];   // (N,) f32
    const float* depth = (const float*)d_in[5];   // (1, 480, 640) f32
    float* out = (float*)d_out;

    k_transpose<<<(int)(HWSZ / 64), dim3(64, 4)>>>(x2d);

    k_fuse<<<(int)(NV / TILE), 256>>>(ppix, scale, mask, pz, depth, out);
}

// round 10
// speedup vs baseline: 2.5046x; 1.0347x over previous
#include <cuda_runtime.h>
#include <cuda_fp16.h>
#include <cuda_bf16.h>
#include <cstdint>

static constexpr int CCH = 64;
static constexpr int HH  = 480;
static constexpr int WW  = 640;
static constexpr long long HWSZ = (long long)HH * WW;   // 307200
static constexpr long long NV   = 256LL * 256 * 32;     // 2097152 voxels
static constexpr int TILE = 256;                        // voxels per block (2 halves)
static constexpr int HALF = 128;
static constexpr int PITCH_H = 66;                      // halves per smem row (132B)
static constexpr int PITCH_W = 33;                      // 32-bit words per row

// Scratch: transposed fp16 features, xTh[pixel * 64 + channel]  (39 MB, L2-resident)
__device__ __align__(16) __half g_xTh[(size_t)HWSZ * CCH];

// ---------------------------------------------------------------------------
// Transpose x2d (C, H*W) f32 -> xTh (H*W, C) f16. Tiled via smem.
// ---------------------------------------------------------------------------
__global__ void __launch_bounds__(256) k_transpose(const float* __restrict__ x2d)
{
    __shared__ float tile[64][65];        // tile[channel][pixel]
    const int pbase = blockIdx.x * 64;
    const int tx = threadIdx.x;   // 0..63
    const int ty = threadIdx.y;   // 0..3
    const int tid  = ty * 64 + tx;
    const int lane = tid & 31;
    const int w    = tid >> 5;    // 0..7

#pragma unroll
    for (int cc = 0; cc < 64; cc += 4)
        tile[cc + ty][tx] = x2d[(long long)(cc + ty) * HWSZ + pbase + tx];
    __syncthreads();

    __half2* xT2 = reinterpret_cast<__half2*>(g_xTh);
#pragma unroll
    for (int it = 0; it < 8; it++) {
        const int p  = it * 8 + w;
        const int c2 = lane * 2;
        const __half2 h = __floats2half2_rn(tile[c2][p], tile[c2 + 1][p]);
        xT2[(long long)(pbase + p) * 32 + lane] = h;
    }
}

__device__ __forceinline__ void sts_row(uint32_t* su, int v, int kk, const uint4& r)
{
    const int wbase = v * PITCH_W + 4 * kk;   // scalar STS.32 x4: conflict-free
    su[wbase + 0] = r.x;
    su[wbase + 1] = r.y;
    su[wbase + 2] = r.z;
    su[wbase + 3] = r.w;
}

// ---------------------------------------------------------------------------
// Fused kernel, 512 threads, 256 voxels/block, 2-half software pipeline:
//   A; bar; Bload(0); Bstore(0); bar; Bload(1); C(0); Bstore(1); bar; C(1)
// Half-1 gather latency hides under half-0's store phase.
// ---------------------------------------------------------------------------
__global__ void __launch_bounds__(512) k_fuse(
    const int*   __restrict__ ppix,     // (N, 2) int32 : x, y
    const int*   __restrict__ scale_p,  // scalar int32
    const int*   __restrict__ mask,     // (N,) int32 (bool)
    const float* __restrict__ pz,       // (N,) float32
    const float* __restrict__ depth,    // (H*W,) float32
    float*       __restrict__ out)      // (64, N) float32
{
    __shared__ __align__(16) __half sm16[TILE][PITCH_H];  // 2 halves of 128 rows
    __shared__ float sm_w[TILE];
    __shared__ int   sm_fidx[TILE];

    uint32_t* su = reinterpret_cast<uint32_t*>(&sm16[0][0]);
    const int tid = threadIdx.x;
    const long long vbase = (long long)blockIdx.x * TILE;

    // ---- Phase A: indices + weights (threads 0..255, one voxel each) ----
    if (tid < TILE) {
        const long long i = vbase + tid;
        const int2 p = reinterpret_cast<const int2*>(ppix)[i];
        const int  m = mask[i];
        const float z = pz[i];
        const int scale = scale_p[0];
        const int di = p.y * WW + p.x;
        const int fi = (scale == 1) ? di : ((p.y / scale) * WW + (p.x / scale));
        sm_fidx[tid] = fi;
        const float dv = m ? __ldg(depth + di) : 0.0f;
        const float d  = z - dv;
        const float gw = __expf(-0.5f * d * d);   // sigma = 1
        sm_w[tid] = m ? ((dv == 0.0f) ? 1.0f : gw) : 0.0f;
    }
    __syncthreads();

    // Gather lane mapping: 8 lanes per 128B fp16 voxel row.
    const int vt = tid >> 3;        // 0..63: voxel slot within pass
    const int kk = tid & 7;         // 0..7 : 16B chunk within row

    uint4 r0, r1;

    // ---- B_load(0) + B_store(0): rows 0..127 ----
    {
        const int va = vt;
        const int vb = 64 + vt;
        r0 = make_uint4(0u, 0u, 0u, 0u);
        r1 = make_uint4(0u, 0u, 0u, 0u);
        if (sm_w[va] != 0.0f)
            r0 = __ldg(reinterpret_cast<const uint4*>(g_xTh + (long long)sm_fidx[va] * CCH) + kk);
        if (sm_w[vb] != 0.0f)
            r1 = __ldg(reinterpret_cast<const uint4*>(g_xTh + (long long)sm_fidx[vb] * CCH) + kk);
        sts_row(su, va, kk, r0);
        sts_row(su, vb, kk, r1);
    }
    __syncthreads();

    // ---- B_load(1): rows 128..255 (latency overlapped with C(0)) ----
    {
        const int va = HALF + vt;
        const int vb = HALF + 64 + vt;
        r0 = make_uint4(0u, 0u, 0u, 0u);
        r1 = make_uint4(0u, 0u, 0u, 0u);
        if (sm_w[va] != 0.0f)
            r0 = __ldg(reinterpret_cast<const uint4*>(g_xTh + (long long)sm_fidx[va] * CCH) + kk);
        if (sm_w[vb] != 0.0f)
            r1 = __ldg(reinterpret_cast<const uint4*>(g_xTh + (long long)sm_fidx[vb] * CCH) + kk);
    }

    // ---- C(0): store half 0 while half-1 gather is in flight ----
    {
        const int vv = tid & (HALF - 1);       // 0..127
        const int cq = tid >> 7;               // 0..3: 16-channel quarter
        const float wv = sm_w[vv];
        float* op = out + vbase + vv;
        const int wrow = vv * PITCH_W;
#pragma unroll
        for (int it = 0; it < 8; it++) {
            const int c = cq * 16 + it * 2;
            const uint32_t bits = su[wrow + (c >> 1)];
            const float2 f = __half22float2(*reinterpret_cast<const __half2*>(&bits));
            __stcs(op + (long long)c * NV,       f.x * wv);
            __stcs(op + (long long)(c + 1) * NV, f.y * wv);
        }
    }

    // ---- B_store(1) ----
    sts_row(su, HALF + vt, kk, r0);
    sts_row(su, HALF + 64 + vt, kk, r1);
    __syncthreads();

    // ---- C(1): store half 1 ----
    {
        const int vv = tid & (HALF - 1);
        const int cq = tid >> 7;
        const int row = HALF + vv;
        const float wv = sm_w[row];
        float* op = out + vbase + row;
        const int wrow = row * PITCH_W;
#pragma unroll
        for (int it = 0; it < 8; it++) {
            const int c = cq * 16 + it * 2;
            const uint32_t bits = su[wrow + (c >> 1)];
            const float2 f = __half22float2(*reinterpret_cast<const __half2*>(&bits));
            __stcs(op + (long long)c * NV,       f.x * wv);
            __stcs(op + (long long)(c + 1) * NV, f.y * wv);
        }
    }
}

extern "C" void kernel_launch(void* const* d_in, const int* in_sizes, int n_in,
                              void* d_out, int out_size)
{
    const float* x2d   = (const float*)d_in[0];   // (64, 480, 640) f32
    const int*   ppix  = (const int*)  d_in[1];   // (N, 2) i32
    const int*   scale = (const int*)  d_in[2];   // scalar i32
    const int*   mask  = (const int*)  d_in[3];   // (N,) i32
    const float* pz    = (const float*)d_in[4];   // (N,) f32
    const float* depth = (const float*)d_in[5];   // (1, 480, 640) f32
    float* out = (float*)d_out;

    k_transpose<<<(int)(HWSZ / 64), dim3(64, 4)>>>(x2d);

    k_fuse<<<(int)(NV / TILE), 512>>>(ppix, scale, mask, pz, depth, out);
}